// round 2
// baseline (speedup 1.0000x reference)
#include <cuda_runtime.h>
#include <cstdint>

#define DEVFN __device__ __forceinline__

constexpr int BN = 16;      // batch
constexpr int CI = 64;      // in channels
constexpr int CO = 64;      // out channels
constexpr int HH = 64;
constexpr int WWI = 64;
constexpr int HW = HH * WWI;          // 4096
constexpr int OC = 18;      // offset channels (2*K*K)
constexpr int CS = 132;     // cols smem row stride (mod 32 == 4, mult of 4 -> conflict-free + float4 aligned)

// Scratch (static device memory; allocation in kernel_launch is forbidden)
__device__ __align__(16) float g_xt [BN * HW * CI];   // x transposed to NHWC, 16.8 MB
__device__ __align__(16) float g_off[BN * HW * OC];   // offsets, [pixel][18]
__device__ __align__(16) float g_wt [9 * CI * CO];    // w_dcn repacked [tap][cin][co]
__device__ __align__(16) float g_wo [9 * CI * OC];    // w_off repacked [tap][cin][oc]

// ---- packed fp32x2 helpers (exact fp32, 2x FFMA throughput on sm_103a) ----
DEVFN unsigned long long pack2(float w) {
    unsigned long long r;
    unsigned int wi = __float_as_uint(w);
    asm("mov.b64 %0, {%1, %1};" : "=l"(r) : "r"(wi));
    return r;
}
DEVFN void fma2(unsigned long long& d, unsigned long long a, unsigned long long b) {
    asm("fma.rn.f32x2 %0, %1, %2, %0;" : "+l"(d) : "l"(a), "l"(b));
}

// ---------------------------------------------------------------------------
// Weight prepack: g_wt[(t*64+cin)*64+co] = w_dcn[co][cin][t]
//                 g_wo[(t*64+cin)*18+oc] = w_off[oc][cin][t]
// ---------------------------------------------------------------------------
__global__ void k_prepack(const float* __restrict__ wdcn, const float* __restrict__ woff) {
    int i = blockIdx.x * blockDim.x + threadIdx.x;
    if (i < 9 * CI * CO) {
        int co  = i & 63;
        int cin = (i >> 6) & 63;
        int t   = i >> 12;
        g_wt[i] = wdcn[(co * CI + cin) * 9 + t];
    }
    int j = i - 9 * CI * CO;
    if (j >= 0 && j < 9 * CI * OC) {
        int oc  = j % OC;
        int r   = j / OC;
        int cin = r & 63;
        int t   = r >> 6;
        g_wo[j] = woff[(oc * CI + cin) * 9 + t];
    }
}

// ---------------------------------------------------------------------------
// NCHW -> NHWC transpose (per batch: 64 x 4096 -> 4096 x 64)
// ---------------------------------------------------------------------------
__global__ void k_transpose(const float* __restrict__ x) {
    __shared__ float s[32][33];
    int b  = blockIdx.z;
    int c0 = blockIdx.y * 32;
    int p0 = blockIdx.x * 32;
    int tx = threadIdx.x, ty = threadIdx.y;   // 32 x 8
    const float* xb = x + (size_t)b * CI * HW;
#pragma unroll
    for (int i = 0; i < 4; i++)
        s[ty + 8 * i][tx] = xb[(size_t)(c0 + ty + 8 * i) * HW + p0 + tx];
    __syncthreads();
    float* xtb = g_xt + (size_t)b * HW * CI;
#pragma unroll
    for (int i = 0; i < 4; i++)
        xtb[(size_t)(p0 + ty + 8 * i) * CI + c0 + tx] = s[tx][ty + 8 * i];
}

// ---------------------------------------------------------------------------
// Offset conv: 3x3, 64->18, pad 1, stride 1.
// Block: 128 threads, 128 pixels (2 image rows). Implicit GEMM 18 x 128 x 576.
// ---------------------------------------------------------------------------
__global__ __launch_bounds__(128, 4) void k_offconv(const float* __restrict__ boff) {
    __shared__ __align__(16) float cols[CI * CS];     // 33.8 KB
    __shared__ float ws[CI * OC];                     // 4.6 KB
    int tid  = threadIdx.x;
    int base = blockIdx.x * 128;          // global pixel base (within one batch: 4096 % 128 == 0)
    int b    = base >> 12;
    int prow = base & 4095;
    const float* xtb = g_xt + (size_t)b * HW * CI;
    int grp = tid >> 3, l8 = tid & 7;     // gather mapping: 16 groups x 8 ch-lanes
    int gco = tid >> 4, gpx = tid & 15;   // gemm mapping (active for tid < 96)
    int px0 = gpx * 8;

    union { unsigned long long u[4]; float f[8]; } acc[3];
#pragma unroll
    for (int i = 0; i < 3; i++)
#pragma unroll
        for (int m = 0; m < 4; m++) acc[i].u[m] = 0ULL;

    for (int t = 0; t < 9; t++) {
        int dy = t / 3 - 1;
        int dx = t - (t / 3) * 3 - 1;
        // stage this tap's weights [cin][18]
        for (int i = tid; i < CI * OC; i += 128) ws[i] = g_wo[t * CI * OC + i];
        // gather integer-tap patch into cols[cin][pixel]
#pragma unroll
        for (int it = 0; it < 8; it++) {
            int p  = grp + 16 * it;
            int pp = prow + p;
            int y  = (pp >> 6) + dy;
            int x  = (pp & 63) + dx;
            bool inb = ((unsigned)y < 64u) && ((unsigned)x < 64u);
            const float* src = xtb + (((y & 63) << 6) + (x & 63)) * 64;
#pragma unroll
            for (int j = 0; j < 8; j++) {
                int c = l8 + 8 * j;
                cols[c * CS + p] = inb ? src[c] : 0.f;
            }
        }
        __syncthreads();
        if (tid < 96) {
            int co0 = gco * 3;
#pragma unroll 4
            for (int k = 0; k < 64; k++) {
                unsigned long long w0 = pack2(ws[k * OC + co0]);
                unsigned long long w1 = pack2(ws[k * OC + co0 + 1]);
                unsigned long long w2 = pack2(ws[k * OC + co0 + 2]);
                union { float4 f; unsigned long long u[2]; } ca, cb;
                ca.f = *(const float4*)&cols[k * CS + px0];
                cb.f = *(const float4*)&cols[k * CS + px0 + 4];
                fma2(acc[0].u[0], w0, ca.u[0]); fma2(acc[0].u[1], w0, ca.u[1]);
                fma2(acc[0].u[2], w0, cb.u[0]); fma2(acc[0].u[3], w0, cb.u[1]);
                fma2(acc[1].u[0], w1, ca.u[0]); fma2(acc[1].u[1], w1, ca.u[1]);
                fma2(acc[1].u[2], w1, cb.u[0]); fma2(acc[1].u[3], w1, cb.u[1]);
                fma2(acc[2].u[0], w2, ca.u[0]); fma2(acc[2].u[1], w2, ca.u[1]);
                fma2(acc[2].u[2], w2, cb.u[0]); fma2(acc[2].u[3], w2, cb.u[1]);
            }
        }
        __syncthreads();
    }
    if (tid < 96) {
        int co0 = gco * 3;
#pragma unroll
        for (int i = 0; i < 3; i++) {
            float bo = boff[co0 + i];
#pragma unroll
            for (int m = 0; m < 8; m++)
                g_off[(size_t)(base + px0 + m) * OC + co0 + i] = acc[i].f[m] + bo;
        }
    }
}

// ---------------------------------------------------------------------------
// Deformable conv main kernel.
// Block: 128 threads, 128 pixels. Per tap: bilinear gather -> cols[cin][px],
// then GEMM 64(co) x 128(px) x 64(cin), rm=8 x rn=8 register tile, f32x2 FMA.
// ---------------------------------------------------------------------------
__global__ __launch_bounds__(128, 4) void k_deform(const float* __restrict__ bdcn,
                                                   float* __restrict__ out) {
    __shared__ __align__(16) float cols[CI * CS];     // 33.8 KB
    __shared__ __align__(16) float ws[32 * CO];       // 8 KB (half-k staging)
    int tid  = threadIdx.x;
    int base = blockIdx.x * 128;
    int b    = base >> 12;
    int prow = base & 4095;
    const float* xtb = g_xt + (size_t)b * HW * CI;
    int grp = tid >> 3, l8 = tid & 7;
    int gco = tid >> 4, gpx = tid & 15;
    int co0 = gco * 8, px0 = gpx * 8;

    union { unsigned long long u[4]; float f[8]; } acc[8];
#pragma unroll
    for (int i = 0; i < 8; i++)
#pragma unroll
        for (int m = 0; m < 4; m++) acc[i].u[m] = 0ULL;

    for (int t = 0; t < 9; t++) {
        float dy = (float)(t / 3 - 1);
        float dx = (float)(t - (t / 3) * 3 - 1);
        // ---- bilinear gather: cols[cin][pixel] for this tap ----
#pragma unroll
        for (int it = 0; it < 8; it++) {
            int p  = grp + 16 * it;
            int pp = prow + p;
            int ho = pp >> 6, wo = pp & 63;
            const float* op = g_off + (size_t)(base + p) * OC + 2 * t;
            float py  = (float)ho + dy + op[0];
            float pxx = (float)wo + dx + op[1];
            float y0f = floorf(py), x0f = floorf(pxx);
            float fy = py - y0f, fx = pxx - x0f;
            int y0 = (int)y0f, x0 = (int)x0f;
            float vy0 = ((unsigned)y0 < 64u) ? 1.f : 0.f;
            float vy1 = ((unsigned)(y0 + 1) < 64u) ? 1.f : 0.f;
            float vx0 = ((unsigned)x0 < 64u) ? 1.f : 0.f;
            float vx1 = ((unsigned)(x0 + 1) < 64u) ? 1.f : 0.f;
            float gy0 = 1.f - fy, gx0 = 1.f - fx;
            float w00 = gy0 * gx0 * vy0 * vx0;
            float w01 = gy0 * fx  * vy0 * vx1;
            float w10 = fy  * gx0 * vy1 * vx0;
            float w11 = fy  * fx  * vy1 * vx1;
            int yc0 = min(max(y0, 0), 63),     yc1 = min(max(y0 + 1, 0), 63);
            int xc0 = min(max(x0, 0), 63),     xc1 = min(max(x0 + 1, 0), 63);
            const float* s00 = xtb + ((yc0 << 6) + xc0) * 64;
            const float* s01 = xtb + ((yc0 << 6) + xc1) * 64;
            const float* s10 = xtb + ((yc1 << 6) + xc0) * 64;
            const float* s11 = xtb + ((yc1 << 6) + xc1) * 64;
#pragma unroll
            for (int j = 0; j < 8; j++) {
                int c = l8 + 8 * j;
                cols[c * CS + p] = w00 * s00[c] + w01 * s01[c] + w10 * s10[c] + w11 * s11[c];
            }
        }
        // ---- GEMM over this tap's 64 cin, staged in two 32-row halves ----
#pragma unroll 1
        for (int half = 0; half < 2; half++) {
            for (int i = tid; i < 512; i += 128)
                ((float4*)ws)[i] = ((const float4*)(g_wt + t * 4096 + half * 2048))[i];
            __syncthreads();   // cols (first half) / ws ready
#pragma unroll 4
            for (int kk = 0; kk < 32; kk++) {
                int k = half * 32 + kk;
                const float* wr = ws + kk * CO + co0;
                unsigned long long wp[8];
#pragma unroll
                for (int i = 0; i < 8; i++) wp[i] = pack2(wr[i]);
                union { float4 f; unsigned long long u[2]; } ca, cb;
                ca.f = *(const float4*)&cols[k * CS + px0];
                cb.f = *(const float4*)&cols[k * CS + px0 + 4];
#pragma unroll
                for (int i = 0; i < 8; i++) {
                    fma2(acc[i].u[0], wp[i], ca.u[0]);
                    fma2(acc[i].u[1], wp[i], ca.u[1]);
                    fma2(acc[i].u[2], wp[i], cb.u[0]);
                    fma2(acc[i].u[3], wp[i], cb.u[1]);
                }
            }
            __syncthreads();   // done with ws (and, on half==1, with cols)
        }
    }
    // ---- epilogue: out[b][co][pixel] (NCHW) ----
#pragma unroll
    for (int i = 0; i < 8; i++) {
        int co = co0 + i;
        float bias = bdcn[co];
        float4 v0, v1;
        v0.x = acc[i].f[0] + bias; v0.y = acc[i].f[1] + bias;
        v0.z = acc[i].f[2] + bias; v0.w = acc[i].f[3] + bias;
        v1.x = acc[i].f[4] + bias; v1.y = acc[i].f[5] + bias;
        v1.z = acc[i].f[6] + bias; v1.w = acc[i].f[7] + bias;
        float* dst = out + ((size_t)b * CO + co) * HW + prow + px0;
        *(float4*)dst       = v0;
        *(float4*)(dst + 4) = v1;
    }
}

// ---------------------------------------------------------------------------
extern "C" void kernel_launch(void* const* d_in, const int* in_sizes, int n_in,
                              void* d_out, int out_size) {
    const float* x     = (const float*)d_in[0];
    const float* w_off = (const float*)d_in[1];
    const float* b_off = (const float*)d_in[2];
    const float* w_dcn = (const float*)d_in[3];
    const float* b_dcn = (const float*)d_in[4];
    (void)in_sizes; (void)n_in; (void)out_size;

    int prepack_total = 9 * CI * CO + 9 * CI * OC;
    k_prepack<<<(prepack_total + 127) / 128, 128>>>(w_dcn, w_off);
    k_transpose<<<dim3(HW / 32, CI / 32, BN), dim3(32, 8)>>>(x);
    k_offconv<<<BN * HW / 128, 128>>>(b_off);
    k_deform<<<BN * HW / 128, 128>>>(b_dcn, (float*)d_out);
}

// round 4
// speedup vs baseline: 1.0874x; 1.0874x over previous
#include <cuda_runtime.h>
#include <cstdint>

#define DEVFN __device__ __forceinline__

constexpr int BN = 16;      // batch
constexpr int CI = 64;      // in channels
constexpr int CO = 64;      // out channels
constexpr int HH = 64;
constexpr int WWI = 64;
constexpr int HW = HH * WWI;          // 4096
constexpr int OC = 18;      // offset channels (2*K*K)
constexpr int OSTR = 20;    // g_off row stride (floats) -> 8B-aligned float2 reads

// Scratch (static device memory; allocation in kernel_launch is forbidden)
__device__ __align__(16) float g_xt [BN * HW * CI];     // x transposed to NHWC
__device__ __align__(16) float g_off[BN * HW * OSTR];   // offsets, [pixel][20]
__device__ __align__(16) float g_wt [9 * CI * CO];      // w_dcn repacked [tap][cin][co]
__device__ __align__(16) float g_wo [9 * CI * OC];      // w_off repacked [tap][cin][oc]

// ---- packed fp32x2 helpers (exact fp32, 2x FFMA throughput on sm_103a) ----
DEVFN unsigned long long pack2(float w) {
    unsigned long long r;
    asm("mov.b64 %0, {%1, %1};" : "=l"(r) : "f"(w));
    return r;
}
DEVFN unsigned long long packpair(float lo, float hi) {
    unsigned long long r;
    asm("mov.b64 %0, {%1, %2};" : "=l"(r) : "f"(lo), "f"(hi));
    return r;
}
DEVFN void fma2(unsigned long long& d, unsigned long long a, unsigned long long b) {
    asm("fma.rn.f32x2 %0, %1, %2, %0;" : "+l"(d) : "l"(a), "l"(b));
}
DEVFN float getc(const float4& v, int q) {
    return q == 0 ? v.x : q == 1 ? v.y : q == 2 ? v.z : v.w;
}

// ---------------------------------------------------------------------------
// Weight prepack
// ---------------------------------------------------------------------------
__global__ void k_prepack(const float* __restrict__ wdcn, const float* __restrict__ woff) {
    int i = blockIdx.x * blockDim.x + threadIdx.x;
    if (i < 9 * CI * CO) {
        int co  = i & 63;
        int cin = (i >> 6) & 63;
        int t   = i >> 12;
        g_wt[i] = wdcn[(co * CI + cin) * 9 + t];
    }
    int j = i - 9 * CI * CO;
    if (j >= 0 && j < 9 * CI * OC) {
        int oc  = j % OC;
        int r   = j / OC;
        int cin = r & 63;
        int t   = r >> 6;
        g_wo[j] = woff[(oc * CI + cin) * 9 + t];
    }
}

// ---------------------------------------------------------------------------
// NCHW -> NHWC transpose
// ---------------------------------------------------------------------------
__global__ void k_transpose(const float* __restrict__ x) {
    __shared__ float s[32][33];
    int b  = blockIdx.z;
    int c0 = blockIdx.y * 32;
    int p0 = blockIdx.x * 32;
    int tx = threadIdx.x, ty = threadIdx.y;   // 32 x 8
    const float* xb = x + (size_t)b * CI * HW;
#pragma unroll
    for (int i = 0; i < 4; i++)
        s[ty + 8 * i][tx] = xb[(size_t)(c0 + ty + 8 * i) * HW + p0 + tx];
    __syncthreads();
    float* xtb = g_xt + (size_t)b * HW * CI;
#pragma unroll
    for (int i = 0; i < 4; i++)
        xtb[(size_t)(p0 + ty + 8 * i) * CI + c0 + tx] = s[tx][ty + 8 * i];
}

// Dual-conflict-free swizzled im2col layout: float4 element (c4, p) lives at
//   colv[p*16 + (c4 ^ ((p>>3)&7))]
// Store phase varies c4 (banks = c4^const), GEMM-load phase varies p>>3
// (banks = tid^const) -> both conflict-free.

// ---------------------------------------------------------------------------
// Offset conv: 3x3, 64->18, pad 1, stride 1. Implicit GEMM 18 x 128 x 576.
// ---------------------------------------------------------------------------
__global__ __launch_bounds__(128, 4) void k_offconv(const float* __restrict__ boff) {
    __shared__ __align__(16) float4 colv[128 * 16];   // 32 KB
    __shared__ float ws[CI * OC];                     // 4.6 KB
    int tid  = threadIdx.x;
    int base = blockIdx.x * 128;
    int b    = base >> 12;
    int prow = base & 4095;
    const float* xtb = g_xt + (size_t)b * HW * CI;
    int lane = tid & 31, wrp = tid >> 5;
    int pxh = lane >> 4, c4 = lane & 15;
    int gco = tid >> 4, gpx = tid & 15;   // gemm mapping (active tid < 96)
    int px0 = gpx * 8;
    int co0 = gco * 3;

    union { unsigned long long u[4]; float f[8]; } acc[3];
#pragma unroll
    for (int i = 0; i < 3; i++)
#pragma unroll
        for (int m = 0; m < 4; m++) acc[i].u[m] = 0ULL;

    for (int t = 0; t < 9; t++) {
        int dy = t / 3 - 1;
        int dx = t - (t / 3) * 3 - 1;
        // stage this tap's weights [cin][18]
        for (int i = tid; i < CI * OC; i += 128) ws[i] = g_wo[t * CI * OC + i];
        // gather integer-tap patch: 2 pixels per warp-iter, float4 per lane
#pragma unroll 4
        for (int it = 0; it < 16; it++) {
            int p  = wrp * 32 + it * 2 + pxh;
            int pp = prow + p;
            int y  = (pp >> 6) + dy;
            int x  = (pp & 63) + dx;
            float4 v = make_float4(0.f, 0.f, 0.f, 0.f);
            if (((unsigned)y < 64u) && ((unsigned)x < 64u))
                v = *(const float4*)(xtb + (((y << 6) + x) << 6) + c4 * 4);
            colv[p * 16 + (c4 ^ ((p >> 3) & 7))] = v;
        }
        __syncthreads();
        if (tid < 96) {
            int sw = (px0 >> 3) & 7;
#pragma unroll 4
            for (int cc = 0; cc < 16; cc++) {
                float4 cv[8];
#pragma unroll
                for (int m = 0; m < 8; m++)
                    cv[m] = colv[(px0 + m) * 16 + (cc ^ sw)];
#pragma unroll
                for (int q = 0; q < 4; q++) {
                    int kk = cc * 4 + q;
                    unsigned long long w0 = pack2(ws[kk * OC + co0]);
                    unsigned long long w1 = pack2(ws[kk * OC + co0 + 1]);
                    unsigned long long w2 = pack2(ws[kk * OC + co0 + 2]);
                    unsigned long long cp[4];
#pragma unroll
                    for (int j = 0; j < 4; j++)
                        cp[j] = packpair(getc(cv[2 * j], q), getc(cv[2 * j + 1], q));
#pragma unroll
                    for (int j = 0; j < 4; j++) {
                        fma2(acc[0].u[j], w0, cp[j]);
                        fma2(acc[1].u[j], w1, cp[j]);
                        fma2(acc[2].u[j], w2, cp[j]);
                    }
                }
            }
        }
        __syncthreads();
    }
    if (tid < 96) {
#pragma unroll
        for (int i = 0; i < 3; i++) {
            float bo = boff[co0 + i];
#pragma unroll
            for (int m = 0; m < 8; m++)
                g_off[(size_t)(base + px0 + m) * OSTR + co0 + i] = acc[i].f[m] + bo;
        }
    }
}

// ---------------------------------------------------------------------------
// Deformable conv main kernel: per tap bilinear gather -> swizzled cols,
// then GEMM 64(co) x 128(px) x 64(cin) with f32x2 FMA.
// ---------------------------------------------------------------------------
__global__ __launch_bounds__(128, 4) void k_deform(const float* __restrict__ bdcn,
                                                   float* __restrict__ out) {
    __shared__ __align__(16) float4 colv[128 * 16];   // 32 KB
    __shared__ __align__(16) float ws[CI * CO];       // 16 KB (full tap)
    int tid  = threadIdx.x;
    int base = blockIdx.x * 128;
    int b    = base >> 12;
    int prow = base & 4095;
    const float* xtb = g_xt + (size_t)b * HW * CI;
    int lane = tid & 31, wrp = tid >> 5;
    int pxh = lane >> 4, c4 = lane & 15;
    int gco = tid >> 4, gpx = tid & 15;
    int co0 = gco * 8, px0 = gpx * 8;

    union { unsigned long long u[4]; float f[8]; } acc[8];
#pragma unroll
    for (int i = 0; i < 8; i++)
#pragma unroll
        for (int m = 0; m < 4; m++) acc[i].u[m] = 0ULL;

    for (int t = 0; t < 9; t++) {
        float dy = (float)(t / 3 - 1);
        float dx = (float)(t - (t / 3) * 3 - 1);
        // ---- bilinear gather: 2 pixels per warp-iter, float4 channels ----
#pragma unroll 4
        for (int it = 0; it < 16; it++) {
            int p  = wrp * 32 + it * 2 + pxh;
            int pp = prow + p;
            int ho = pp >> 6, wo = pp & 63;
            float2 o2 = *(const float2*)(g_off + (size_t)(base + p) * OSTR + 2 * t);
            float py  = (float)ho + dy + o2.x;
            float pxx = (float)wo + dx + o2.y;
            float y0f = floorf(py), x0f = floorf(pxx);
            float fy = py - y0f, fx = pxx - x0f;
            int y0 = (int)y0f, x0 = (int)x0f;
            float vy0 = ((unsigned)y0 < 64u) ? 1.f : 0.f;
            float vy1 = ((unsigned)(y0 + 1) < 64u) ? 1.f : 0.f;
            float vx0 = ((unsigned)x0 < 64u) ? 1.f : 0.f;
            float vx1 = ((unsigned)(x0 + 1) < 64u) ? 1.f : 0.f;
            float gy0 = 1.f - fy, gx0 = 1.f - fx;
            float w00 = gy0 * gx0 * vy0 * vx0;
            float w01 = gy0 * fx  * vy0 * vx1;
            float w10 = fy  * gx0 * vy1 * vx0;
            float w11 = fy  * fx  * vy1 * vx1;
            int yc0 = min(max(y0, 0), 63),     yc1 = min(max(y0 + 1, 0), 63);
            int xc0 = min(max(x0, 0), 63),     xc1 = min(max(x0 + 1, 0), 63);
            const float4* s00 = (const float4*)(xtb + (((yc0 << 6) + xc0) << 6)) + c4;
            const float4* s01 = (const float4*)(xtb + (((yc0 << 6) + xc1) << 6)) + c4;
            const float4* s10 = (const float4*)(xtb + (((yc1 << 6) + xc0) << 6)) + c4;
            const float4* s11 = (const float4*)(xtb + (((yc1 << 6) + xc1) << 6)) + c4;
            float4 v00 = *s00, v01 = *s01, v10 = *s10, v11 = *s11;
            float4 r;
            r.x = w00 * v00.x + w01 * v01.x + w10 * v10.x + w11 * v11.x;
            r.y = w00 * v00.y + w01 * v01.y + w10 * v10.y + w11 * v11.y;
            r.z = w00 * v00.z + w01 * v01.z + w10 * v10.z + w11 * v11.z;
            r.w = w00 * v00.w + w01 * v01.w + w10 * v10.w + w11 * v11.w;
            colv[p * 16 + (c4 ^ ((p >> 3) & 7))] = r;
        }
        // ---- stage full tap weights [cin][co] (16 KB) ----
        {
            const float4* src = (const float4*)(g_wt + t * CI * CO);
#pragma unroll
            for (int r = 0; r < 8; r++)
                ((float4*)ws)[tid + 128 * r] = src[tid + 128 * r];
        }
        __syncthreads();
        // ---- GEMM over this tap's 64 cin ----
        {
            int sw = (px0 >> 3) & 7;
#pragma unroll 4
            for (int cc = 0; cc < 16; cc++) {
                float4 cv[8];
#pragma unroll
                for (int m = 0; m < 8; m++)
                    cv[m] = colv[(px0 + m) * 16 + (cc ^ sw)];
#pragma unroll
                for (int q = 0; q < 4; q++) {
                    int kk = cc * 4 + q;
                    const float* wr = ws + kk * CO + co0;
                    float4 wa = *(const float4*)wr;
                    float4 wb = *(const float4*)(wr + 4);
                    unsigned long long wp[8];
                    wp[0] = pack2(wa.x); wp[1] = pack2(wa.y);
                    wp[2] = pack2(wa.z); wp[3] = pack2(wa.w);
                    wp[4] = pack2(wb.x); wp[5] = pack2(wb.y);
                    wp[6] = pack2(wb.z); wp[7] = pack2(wb.w);
                    unsigned long long cp[4];
#pragma unroll
                    for (int j = 0; j < 4; j++)
                        cp[j] = packpair(getc(cv[2 * j], q), getc(cv[2 * j + 1], q));
#pragma unroll
                    for (int i = 0; i < 8; i++) {
                        fma2(acc[i].u[0], wp[i], cp[0]);
                        fma2(acc[i].u[1], wp[i], cp[1]);
                        fma2(acc[i].u[2], wp[i], cp[2]);
                        fma2(acc[i].u[3], wp[i], cp[3]);
                    }
                }
            }
        }
        __syncthreads();   // colv consumed; safe to overwrite next tap
    }
    // ---- epilogue: out[b][co][pixel] (NCHW) ----
#pragma unroll
    for (int i = 0; i < 8; i++) {
        int co = co0 + i;
        float bias = bdcn[co];
        float4 v0, v1;
        v0.x = acc[i].f[0] + bias; v0.y = acc[i].f[1] + bias;
        v0.z = acc[i].f[2] + bias; v0.w = acc[i].f[3] + bias;
        v1.x = acc[i].f[4] + bias; v1.y = acc[i].f[5] + bias;
        v1.z = acc[i].f[6] + bias; v1.w = acc[i].f[7] + bias;
        float* dst = out + ((size_t)b * CO + co) * HW + prow + px0;
        *(float4*)dst       = v0;
        *(float4*)(dst + 4) = v1;
    }
}

// ---------------------------------------------------------------------------
extern "C" void kernel_launch(void* const* d_in, const int* in_sizes, int n_in,
                              void* d_out, int out_size) {
    const float* x     = (const float*)d_in[0];
    const float* w_off = (const float*)d_in[1];
    const float* b_off = (const float*)d_in[2];
    const float* w_dcn = (const float*)d_in[3];
    const float* b_dcn = (const float*)d_in[4];
    (void)in_sizes; (void)n_in; (void)out_size;

    int prepack_total = 9 * CI * CO + 9 * CI * OC;
    k_prepack<<<(prepack_total + 127) / 128, 128>>>(w_dcn, w_off);
    k_transpose<<<dim3(HW / 32, CI / 32, BN), dim3(32, 8)>>>(x);
    k_offconv<<<BN * HW / 128, 128>>>(b_off);
    k_deform<<<BN * HW / 128, 128>>>(b_dcn, (float*)d_out);
}